// round 16
// baseline (speedup 1.0000x reference)
#include <cuda_runtime.h>
#include <cuda_bf16.h>
#include <cstdint>

#define NN 50000
#define NE 800000
#define NG 1024
#define NFEAT 32
#define NREL 4
#define NH 64
#define NO 16
#define MAXDEG 10
#define NTILES ((NN + 127) / 128 + MAXDEG)   // 401: upper bound on total bucket tiles

// padded bf16 tile stride (elements): 70 -> 35 words/row; fill-store bank = 3*row (coprime 32) -> conflict-free
#define AST 70
// dynamic smem layout (bytes)
#define OFF_NODES 0
#define OFF_AHI   1024
#define OFF_ALO   (OFF_AHI + 128 * AST * 2)   // 18944
#define OFF_BHI   (OFF_ALO + 128 * AST * 2)   // 36864
#define OFF_BLO   (OFF_BHI + 64 * AST * 2)    // 45824
#define SMEM_SZ   (OFF_BLO + 64 * AST * 2)    // 54784

// ---------------- scratch (device globals) ----------------
__device__ float g_h[NN * NH];
__device__ float g_hmid[NN * NH];
__device__ float g_aggm[NN * NH];
__device__ float g_agg[NN * NREL * NH];
__device__ float g_pool[NG * NH];
__device__ float g_invw[NN * NREL];
__device__ int   g_cnt[NN * NREL];
__device__ int   g_off4[NN * NREL];
__device__ int   g_cur4[NN * NREL];
__device__ int   g_indeg[NN];
__device__ int   g_off[NN];
__device__ int   g_csr[NE];
__device__ int   g_rel[NE];
__device__ int   g_bcnt[MAXDEG + 1];
__device__ int   g_bnodes[(MAXDEG + 1) * NN];  // fixed region per degree bucket
__device__ int   g_total;

// ---------------- mma.sync helper ----------------
static __device__ __forceinline__ void mma16816(float* c, const uint32_t* a, const uint32_t* b) {
    asm volatile(
        "mma.sync.aligned.m16n8k16.row.col.f32.bf16.bf16.f32 "
        "{%0,%1,%2,%3}, {%4,%5,%6,%7}, {%8,%9}, {%0,%1,%2,%3};\n"
        : "+f"(c[0]), "+f"(c[1]), "+f"(c[2]), "+f"(c[3])
        : "r"(a[0]), "r"(a[1]), "r"(a[2]), "r"(a[3]), "r"(b[0]), "r"(b[1]));
}
static __device__ __forceinline__ uint32_t lds_u32(const __nv_bfloat16* p) {
    return *reinterpret_cast<const uint32_t*>(p);
}

// split one float4 (row segment of 4 k-values) into bf16 hi/lo into padded tiles
static __device__ __forceinline__ void split_store4(__nv_bfloat16* Ah, __nv_bfloat16* Al,
                                                    int row, int k, float4 v) {
    __nv_bfloat16 hx = __float2bfloat16_rn(v.x);
    __nv_bfloat16 hy = __float2bfloat16_rn(v.y);
    __nv_bfloat16 hz = __float2bfloat16_rn(v.z);
    __nv_bfloat16 hw = __float2bfloat16_rn(v.w);
    __nv_bfloat16 lx = __float2bfloat16_rn(v.x - __bfloat162float(hx));
    __nv_bfloat16 ly = __float2bfloat16_rn(v.y - __bfloat162float(hy));
    __nv_bfloat16 lz = __float2bfloat16_rn(v.z - __bfloat162float(hz));
    __nv_bfloat16 lw = __float2bfloat16_rn(v.w - __bfloat162float(hw));
    __nv_bfloat162* ph = reinterpret_cast<__nv_bfloat162*>(Ah + row * AST + k);
    __nv_bfloat162* pl = reinterpret_cast<__nv_bfloat162*>(Al + row * AST + k);
    ph[0] = __nv_bfloat162(hx, hy); ph[1] = __nv_bfloat162(hz, hw);
    pl[0] = __nv_bfloat162(lx, ly); pl[1] = __nv_bfloat162(lz, lw);
}

// transpose-load 64x64 fp32 weight chunk [k][n] -> [n][k] bf16 hi/lo padded tiles
static __device__ __forceinline__ void load_b_chunk(__nv_bfloat16* Bh, __nv_bfloat16* Bl,
                                                    const float* __restrict__ bsrc, int tid) {
#pragma unroll
    for (int i = 0; i < 32; i++) {
        int idx = i * 128 + tid;
        int k = idx >> 6, n = idx & 63;
        float val = __ldg(&bsrc[k * 64 + n]);
        __nv_bfloat16 hb = __float2bfloat16_rn(val);
        __nv_bfloat16 lb = __float2bfloat16_rn(val - __bfloat162float(hb));
        Bh[n * AST + k] = hb;
        Bl[n * AST + k] = lb;
    }
}

// warp-level 32x64 mma over one K=64 chunk; acc[2][8][4]
static __device__ __forceinline__ void mma_chunk(float acc[2][8][4],
                                                 const __nv_bfloat16* Ah, const __nv_bfloat16* Al,
                                                 const __nv_bfloat16* Bh, const __nv_bfloat16* Bl,
                                                 int wid, int lane) {
    int g = lane >> 2, t = lane & 3;
#pragma unroll
    for (int ks = 0; ks < 4; ks++) {
        int kb = ks * 16 + 2 * t;
        uint32_t ah[2][4], al[2][4];
#pragma unroll
        for (int mt = 0; mt < 2; mt++) {
            const __nv_bfloat16* ph = Ah + (wid * 32 + mt * 16 + g) * AST + kb;
            const __nv_bfloat16* pl = Al + (wid * 32 + mt * 16 + g) * AST + kb;
            ah[mt][0] = lds_u32(ph);            ah[mt][1] = lds_u32(ph + 8 * AST);
            ah[mt][2] = lds_u32(ph + 8);        ah[mt][3] = lds_u32(ph + 8 * AST + 8);
            al[mt][0] = lds_u32(pl);            al[mt][1] = lds_u32(pl + 8 * AST);
            al[mt][2] = lds_u32(pl + 8);        al[mt][3] = lds_u32(pl + 8 * AST + 8);
        }
#pragma unroll
        for (int nt = 0; nt < 8; nt++) {
            const __nv_bfloat16* qh = Bh + (nt * 8 + g) * AST + kb;
            const __nv_bfloat16* ql = Bl + (nt * 8 + g) * AST + kb;
            uint32_t bh[2] = {lds_u32(qh), lds_u32(qh + 8)};
            uint32_t bl[2] = {lds_u32(ql), lds_u32(ql + 8)};
#pragma unroll
            for (int mt = 0; mt < 2; mt++) {
                mma16816(acc[mt][nt], ah[mt], bh);
                mma16816(acc[mt][nt], ah[mt], bl);
                mma16816(acc[mt][nt], al[mt], bh);
            }
        }
    }
}

// shared mainloop for mf kernels: bucket mapping + A/B fill + mma; returns d (or -1)
static __device__ __forceinline__ int mf_mainloop(float acc[2][8][4], int* nodes, char* smem,
                                                  const float* __restrict__ Wl,
                                                  const float* __restrict__ Wr) {
    int bid = blockIdx.x;
    int d = -1, t0 = 0, acc0 = 0;
#pragma unroll
    for (int dd = 0; dd <= MAXDEG; dd++) {
        int tiles = (g_bcnt[dd] + 127) >> 7;
        if (d < 0 && bid < acc0 + tiles) { d = dd; t0 = (bid - acc0) * 128; }
        acc0 += tiles;
    }
    if (d < 0) return -1;
    int cnt = g_bcnt[d];

    __nv_bfloat16* Ah = (__nv_bfloat16*)(smem + OFF_AHI);
    __nv_bfloat16* Al = (__nv_bfloat16*)(smem + OFF_ALO);
    __nv_bfloat16* Bh = (__nv_bfloat16*)(smem + OFF_BHI);
    __nv_bfloat16* Bl = (__nv_bfloat16*)(smem + OFF_BLO);
    int tid = threadIdx.x, wid = tid >> 5, lane = tid & 31;
    {
        int idx = t0 + tid;
        nodes[tid] = (idx < cnt) ? g_bnodes[d * NN + idx] : -1;
    }
    __syncthreads();
    int mynode = nodes[tid];

#pragma unroll
    for (int a = 0; a < 2; a++)
#pragma unroll
        for (int b = 0; b < 8; b++)
#pragma unroll
            for (int cc = 0; cc < 4; cc++) acc[a][b][cc] = 0.f;

    for (int c = 0; c < 2; c++) {
        if (c) __syncthreads();
        if (mynode >= 0) {
            const float4* src = c ? (const float4*)(g_hmid + (size_t)mynode * NH)
                                  : (const float4*)(g_aggm + (size_t)mynode * NH);
            bool rl = (c == 1);
#pragma unroll
            for (int q = 0; q < 16; q++) {
                float4 v = src[q];
                if (rl) { v.x = fmaxf(v.x, 0.f); v.y = fmaxf(v.y, 0.f);
                          v.z = fmaxf(v.z, 0.f); v.w = fmaxf(v.w, 0.f); }
                split_store4(Ah, Al, tid, q * 4, v);
            }
        } else {
#pragma unroll
            for (int q = 0; q < 16; q++)
                split_store4(Ah, Al, tid, q * 4, make_float4(0.f, 0.f, 0.f, 0.f));
        }
        load_b_chunk(Bh, Bl, (c ? Wr : Wl) + d * NH * NH, tid);
        __syncthreads();
        mma_chunk(acc, Ah, Al, Bh, Bl, wid, lane);
    }
    return d;
}

// ---------------- zero scratch ----------------
__global__ void zero_kernel() {
    int i = blockIdx.x * 256 + threadIdx.x;
    if (i < NN * NREL) { g_cnt[i] = 0; g_cur4[i] = 0; }
    if (i < NG * NH) g_pool[i] = 0.f;
    if (i <= MAXDEG) g_bcnt[i] = 0;
    if (i == 0) g_total = 0;
}

// ---------------- node init ----------------
__global__ void node_init_kernel(const float* __restrict__ x, const float* __restrict__ emb) {
    int n = blockIdx.x * 128 + threadIdx.x;
    if (n >= NN) return;
    const float4* xr = (const float4*)(x + (size_t)n * NFEAT);
    float best = -1e30f; int bi = 0;
#pragma unroll
    for (int q = 0; q < NFEAT / 4; q++) {
        float4 v = xr[q];
        if (v.x > best) { best = v.x; bi = q * 4 + 0; }
        if (v.y > best) { best = v.y; bi = q * 4 + 1; }
        if (v.z > best) { best = v.z; bi = q * 4 + 2; }
        if (v.w > best) { best = v.w; bi = q * 4 + 3; }
    }
    const float4* er = (const float4*)(emb + bi * NH);
    float4* hr = (float4*)(g_h + (size_t)n * NH);
#pragma unroll
    for (int q = 0; q < NH / 4; q++) hr[q] = er[q];
}

// ---------------- edge prep ----------------
__global__ void edge_prep_kernel(const float* __restrict__ ea, const int* __restrict__ ei) {
    int e = blockIdx.x * 256 + threadIdx.x;
    if (e >= NE) return;
    float4 a = ((const float4*)ea)[e];
    int rel = 0; float best = a.x;
    if (a.y > best) { best = a.y; rel = 1; }
    if (a.z > best) { best = a.z; rel = 2; }
    if (a.w > best) { best = a.w; rel = 3; }
    g_rel[e] = rel;
    atomicAdd(&g_cnt[ei[NE + e] * NREL + rel], 1);
}

// ---------------- node meta: inv weights, CSR offsets, degree-bucket count+fill fused ----------------
__global__ void node_meta_kernel() {
    int n = blockIdx.x * 256 + threadIdx.x;
    int lane = threadIdx.x & 31;
    bool valid = n < NN;
    int c0 = 0, c1 = 0, c2 = 0, c3 = 0;
    if (valid) {
        c0 = g_cnt[n * NREL + 0]; c1 = g_cnt[n * NREL + 1];
        c2 = g_cnt[n * NREL + 2]; c3 = g_cnt[n * NREL + 3];
    }
    int ind = c0 + c1 + c2 + c3;
    if (valid) {
        g_invw[n * NREL + 0] = c0 ? 1.0f / (float)c0 : 0.f;
        g_invw[n * NREL + 1] = c1 ? 1.0f / (float)c1 : 0.f;
        g_invw[n * NREL + 2] = c2 ? 1.0f / (float)c2 : 0.f;
        g_invw[n * NREL + 3] = c3 ? 1.0f / (float)c3 : 0.f;
        g_indeg[n] = ind;
    }
    int incl = ind;
#pragma unroll
    for (int o = 1; o < 32; o <<= 1) {
        int t = __shfl_up_sync(0xffffffffu, incl, o);
        if (lane >= o) incl += t;
    }
    int wsum = __shfl_sync(0xffffffffu, incl, 31);
    int base = 0;
    if (lane == 0) base = atomicAdd(&g_total, wsum);
    base = __shfl_sync(0xffffffffu, base, 0);
    if (valid) {
        int off = base + incl - ind;
        g_off[n] = off;
        g_off4[n * NREL + 0] = off;
        g_off4[n * NREL + 1] = off + c0;
        g_off4[n * NREL + 2] = off + c0 + c1;
        g_off4[n * NREL + 3] = off + c0 + c1 + c2;
    }
    int d = min(ind, MAXDEG);
    unsigned vm = __ballot_sync(0xffffffffu, valid);
    unsigned m = __match_any_sync(0xffffffffu, d) & vm;
    if (valid) {
        int leader = __ffs(m) - 1;
        int rank = __popc(m & ((1u << lane) - 1));
        int bbase = 0;
        if (lane == leader) bbase = atomicAdd(&g_bcnt[d], __popc(m));
        bbase = __shfl_sync(0xffffffffu, bbase, leader);
        g_bnodes[d * NN + bbase + rank] = n;
    }
}

__global__ void csr_fill_kernel(const int* __restrict__ ei) {
    int e = blockIdx.x * 256 + threadIdx.x;
    if (e >= NE) return;
    int t = ei[NE + e];
    int slot = t * NREL + g_rel[e];
    int pos = g_off4[slot] + atomicAdd(&g_cur4[slot], 1);
    g_csr[pos] = ei[e];
}

// ---------------- RGCN gather: one node per warp, float2 per lane ----------------
__global__ __launch_bounds__(256) void rgcn_gather_kernel() {
    int wid = threadIdx.x >> 5, lane = threadIdx.x & 31;
    int node = blockIdx.x * 8 + wid;
    if (node >= NN) return;
    const float2* h2 = (const float2*)g_h;   // row stride 32 float2
    const int* off4 = g_off4 + node * NREL;
    const int* cnt4 = g_cnt + node * NREL;
    const float* iw = g_invw + node * NREL;
    float2* o = (float2*)(g_agg + ((size_t)node * NREL) * NH) + lane;
#pragma unroll
    for (int r = 0; r < NREL; r++) {
        int beg = off4[r];
        int end = beg + cnt4[r];
        float a0 = 0.f, a1 = 0.f;
        int i = beg;
        for (; i + 4 <= end; i += 4) {
            int s0 = __ldg(&g_csr[i]),     s1 = __ldg(&g_csr[i + 1]);
            int s2 = __ldg(&g_csr[i + 2]), s3 = __ldg(&g_csr[i + 3]);
            float2 v0 = __ldg(&h2[s0 * 32 + lane]);
            float2 v1 = __ldg(&h2[s1 * 32 + lane]);
            float2 v2 = __ldg(&h2[s2 * 32 + lane]);
            float2 v3 = __ldg(&h2[s3 * 32 + lane]);
            a0 += fmaxf(v0.x, 0.f) + fmaxf(v1.x, 0.f) + fmaxf(v2.x, 0.f) + fmaxf(v3.x, 0.f);
            a1 += fmaxf(v0.y, 0.f) + fmaxf(v1.y, 0.f) + fmaxf(v2.y, 0.f) + fmaxf(v3.y, 0.f);
        }
        for (; i < end; i++) {
            float2 v = __ldg(&h2[__ldg(&g_csr[i]) * 32 + lane]);
            a0 += fmaxf(v.x, 0.f);
            a1 += fmaxf(v.y, 0.f);
        }
        float w = iw[r];
        o[r * 32] = make_float2(a0 * w, a1 * w);
    }
}

// ---------------- RGCN GEMM via mma.sync bf16-split (128 threads, 5 K-chunks) ----------------
__global__ __launch_bounds__(128) void rgcn_gemm_tc(const float* __restrict__ W,
                                                    const float* __restrict__ Wroot,
                                                    const float* __restrict__ bias) {
    extern __shared__ __align__(16) char smem[];
    __nv_bfloat16* Ah = (__nv_bfloat16*)(smem + OFF_AHI);
    __nv_bfloat16* Al = (__nv_bfloat16*)(smem + OFF_ALO);
    __nv_bfloat16* Bh = (__nv_bfloat16*)(smem + OFF_BHI);
    __nv_bfloat16* Bl = (__nv_bfloat16*)(smem + OFF_BLO);
    int tid = threadIdx.x, wid = tid >> 5, lane = tid & 31;
    int row = blockIdx.x * 128 + tid;

    float acc[2][8][4];
#pragma unroll
    for (int a = 0; a < 2; a++)
#pragma unroll
        for (int b = 0; b < 8; b++)
#pragma unroll
            for (int c = 0; c < 4; c++) acc[a][b][c] = 0.f;

    for (int c = 0; c < 5; c++) {
        if (c) __syncthreads();
        if (row < NN) {
            const float4* src = (c < 4)
                ? (const float4*)(g_agg + ((size_t)row * NREL + c) * NH)
                : (const float4*)(g_h + (size_t)row * NH);
            bool rl = (c == 4);
#pragma unroll
            for (int q = 0; q < 16; q++) {
                float4 v = src[q];
                if (rl) { v.x = fmaxf(v.x, 0.f); v.y = fmaxf(v.y, 0.f);
                          v.z = fmaxf(v.z, 0.f); v.w = fmaxf(v.w, 0.f); }
                split_store4(Ah, Al, tid, q * 4, v);
            }
        } else {
#pragma unroll
            for (int q = 0; q < 16; q++)
                split_store4(Ah, Al, tid, q * 4, make_float4(0.f, 0.f, 0.f, 0.f));
        }
        load_b_chunk(Bh, Bl, (c < 4) ? (W + c * NH * NH) : Wroot, tid);
        __syncthreads();
        mma_chunk(acc, Ah, Al, Bh, Bl, wid, lane);
    }

    int g = lane >> 2, t = lane & 3;
#pragma unroll
    for (int mt = 0; mt < 2; mt++) {
        int r0 = blockIdx.x * 128 + wid * 32 + mt * 16 + g;
        int r1 = r0 + 8;
#pragma unroll
        for (int nt = 0; nt < 8; nt++) {
            int col = nt * 8 + 2 * t;
            float b0 = __ldg(&bias[col]), b1 = __ldg(&bias[col + 1]);
            if (r0 < NN)
                *(float2*)(g_hmid + (size_t)r0 * NH + col) =
                    make_float2(acc[mt][nt][0] + b0, acc[mt][nt][1] + b1);
            if (r1 < NN)
                *(float2*)(g_hmid + (size_t)r1 * NH + col) =
                    make_float2(acc[mt][nt][2] + b0, acc[mt][nt][3] + b1);
        }
    }
}

// ---------------- MFConv gather: one node per warp, float2 per lane ----------------
__global__ __launch_bounds__(256) void mf_gather_kernel() {
    int wid = threadIdx.x >> 5, lane = threadIdx.x & 31;
    int node = blockIdx.x * 8 + wid;
    if (node >= NN) return;
    const float2* h2 = (const float2*)g_hmid;
    int beg = g_off[node];
    int end = beg + g_indeg[node];
    float a0 = 0.f, a1 = 0.f;
    int i = beg;
    for (; i + 4 <= end; i += 4) {
        int s0 = __ldg(&g_csr[i]),     s1 = __ldg(&g_csr[i + 1]);
        int s2 = __ldg(&g_csr[i + 2]), s3 = __ldg(&g_csr[i + 3]);
        float2 v0 = __ldg(&h2[s0 * 32 + lane]);
        float2 v1 = __ldg(&h2[s1 * 32 + lane]);
        float2 v2 = __ldg(&h2[s2 * 32 + lane]);
        float2 v3 = __ldg(&h2[s3 * 32 + lane]);
        a0 += fmaxf(v0.x, 0.f) + fmaxf(v1.x, 0.f) + fmaxf(v2.x, 0.f) + fmaxf(v3.x, 0.f);
        a1 += fmaxf(v0.y, 0.f) + fmaxf(v1.y, 0.f) + fmaxf(v2.y, 0.f) + fmaxf(v3.y, 0.f);
    }
    for (; i < end; i++) {
        float2 v = __ldg(&h2[__ldg(&g_csr[i]) * 32 + lane]);
        a0 += fmaxf(v.x, 0.f);
        a1 += fmaxf(v.y, 0.f);
    }
    ((float2*)(g_aggm + (size_t)node * NH))[lane] = make_float2(a0, a1);
}

// ---------------- MFConv GEMM (block 0): writes g_h ----------------
__global__ __launch_bounds__(128) void mf_gemm_tc(const float* __restrict__ Wl,
                                                  const float* __restrict__ blv,
                                                  const float* __restrict__ Wr) {
    extern __shared__ __align__(16) char smem[];
    int* nodes = (int*)(smem + OFF_NODES);
    float acc[2][8][4];
    int d = mf_mainloop(acc, nodes, smem, Wl, Wr);
    if (d < 0) return;

    int lane = threadIdx.x & 31, wid = threadIdx.x >> 5;
    int g = lane >> 2, t = lane & 3;
    const float* bb = blv + d * NH;
#pragma unroll
    for (int mt = 0; mt < 2; mt++) {
        int i0 = wid * 32 + mt * 16 + g;
        int n0 = nodes[i0], n1 = nodes[i0 + 8];
#pragma unroll
        for (int nt = 0; nt < 8; nt++) {
            int col = nt * 8 + 2 * t;
            float b0 = __ldg(&bb[col]), b1 = __ldg(&bb[col + 1]);
            if (n0 >= 0)
                *(float2*)(g_h + (size_t)n0 * NH + col) =
                    make_float2(acc[mt][nt][0] + b0, acc[mt][nt][1] + b1);
            if (n1 >= 0)
                *(float2*)(g_h + (size_t)n1 * NH + col) =
                    make_float2(acc[mt][nt][2] + b0, acc[mt][nt][3] + b1);
        }
    }
}

// ---------------- MFConv GEMM (final block): pools directly into g_pool ----------------
__global__ __launch_bounds__(128) void mf_gemm_pool_tc(const float* __restrict__ Wl,
                                                       const float* __restrict__ blv,
                                                       const float* __restrict__ Wr,
                                                       const int* __restrict__ batch) {
    extern __shared__ __align__(16) char smem[];
    int* nodes = (int*)(smem + OFF_NODES);
    float acc[2][8][4];
    int d = mf_mainloop(acc, nodes, smem, Wl, Wr);
    if (d < 0) return;

    int lane = threadIdx.x & 31, wid = threadIdx.x >> 5;
    int g = lane >> 2, t = lane & 3;
    const float* bb = blv + d * NH;
#pragma unroll
    for (int mt = 0; mt < 2; mt++) {
        int i0 = wid * 32 + mt * 16 + g;
        int n0 = nodes[i0], n1 = nodes[i0 + 8];
        int p0 = (n0 >= 0) ? __ldg(&batch[n0]) * NH : -1;
        int p1 = (n1 >= 0) ? __ldg(&batch[n1]) * NH : -1;
#pragma unroll
        for (int nt = 0; nt < 8; nt++) {
            int col = nt * 8 + 2 * t;
            float b0 = __ldg(&bb[col]), b1 = __ldg(&bb[col + 1]);
            if (p0 >= 0) {
                atomicAdd(&g_pool[p0 + col], acc[mt][nt][0] + b0);
                atomicAdd(&g_pool[p0 + col + 1], acc[mt][nt][1] + b1);
            }
            if (p1 >= 0) {
                atomicAdd(&g_pool[p1 + col], acc[mt][nt][2] + b0);
                atomicAdd(&g_pool[p1 + col + 1], acc[mt][nt][3] + b1);
            }
        }
    }
}

// ---------------- head MLP ----------------
__global__ __launch_bounds__(256) void mlp_kernel(const float* __restrict__ l1w, const float* __restrict__ l1b,
                                                  const float* __restrict__ l2w, const float* __restrict__ l2b,
                                                  float* __restrict__ out) {
    __shared__ float s1[NH * NH];
    __shared__ float s2[NH * NO];
    __shared__ float sg[8][NH];
    int tid = threadIdx.x, lane = tid & 31, w = tid >> 5;
#pragma unroll
    for (int i = 0; i < 16; i++) s1[i * 256 + tid] = l1w[i * 256 + tid];
#pragma unroll
    for (int i = 0; i < 4; i++) s2[i * 256 + tid] = l2w[i * 256 + tid];
    int gidx = blockIdx.x * 8 + w;
    sg[w][lane] = g_pool[gidx * NH + lane];
    sg[w][lane + 32] = g_pool[gidx * NH + lane + 32];
    __syncthreads();
    float t0 = l1b[lane], t1 = l1b[lane + 32];
#pragma unroll 8
    for (int k = 0; k < NH; k++) {
        float gv = sg[w][k];
        t0 += gv * s1[k * NH + lane];
        t1 += gv * s1[k * NH + lane + 32];
    }
    t0 = fmaxf(t0, 0.f); t1 = fmaxf(t1, 0.f);
    __syncwarp();
    sg[w][lane] = t0; sg[w][lane + 32] = t1;
    __syncwarp();
    if (lane < NO) {
        float acc = l2b[lane];
#pragma unroll 8
        for (int j = 0; j < NH; j++) acc += sg[w][j] * s2[j * NO + lane];
        out[gidx * NO + lane] = acc;
    }
}

// ---------------- launch ----------------
extern "C" void kernel_launch(void* const* d_in, const int* in_sizes, int n_in,
                              void* d_out, int out_size) {
    const float *x, *ea, *emb, *l1w, *l1b, *l2w, *l2b;
    const int *ei, *batch;
    const float *rw[2], *rro[2], *rb[2], *wl[2], *bll[2], *wr[2];

    if (in_sizes[1] == NE * NREL) {
        x = (const float*)d_in[0];  ea = (const float*)d_in[1];
        ei = (const int*)d_in[2];   batch = (const int*)d_in[3];
        emb = (const float*)d_in[4];
        l1w = (const float*)d_in[5]; l1b = (const float*)d_in[6];
        l2w = (const float*)d_in[7]; l2b = (const float*)d_in[8];
        for (int b = 0; b < 2; b++) {
            int k = 9 + 6 * b;
            rw[b]  = (const float*)d_in[k + 0];
            rro[b] = (const float*)d_in[k + 1];
            rb[b]  = (const float*)d_in[k + 2];
            wl[b]  = (const float*)d_in[k + 3];
            bll[b] = (const float*)d_in[k + 4];
            wr[b]  = (const float*)d_in[k + 5];
        }
    } else {
        x = (const float*)d_in[0];  ei = (const int*)d_in[1];
        ea = (const float*)d_in[2]; batch = (const int*)d_in[3];
        emb = (const float*)d_in[4];
        for (int b = 0; b < 2; b++) {
            int k = 5 + 6 * b;
            rw[b]  = (const float*)d_in[k + 0];
            rro[b] = (const float*)d_in[k + 1];
            rb[b]  = (const float*)d_in[k + 2];
            wl[b]  = (const float*)d_in[k + 3];
            bll[b] = (const float*)d_in[k + 4];
            wr[b]  = (const float*)d_in[k + 5];
        }
        l1w = (const float*)d_in[17]; l1b = (const float*)d_in[18];
        l2w = (const float*)d_in[19]; l2b = (const float*)d_in[20];
    }
    float* out = (float*)d_out;

    cudaFuncSetAttribute(rgcn_gemm_tc, cudaFuncAttributeMaxDynamicSharedMemorySize, SMEM_SZ);
    cudaFuncSetAttribute(mf_gemm_tc, cudaFuncAttributeMaxDynamicSharedMemorySize, SMEM_SZ);
    cudaFuncSetAttribute(mf_gemm_pool_tc, cudaFuncAttributeMaxDynamicSharedMemorySize, SMEM_SZ);

    zero_kernel<<<(NN * NREL + 255) / 256, 256>>>();
    node_init_kernel<<<(NN + 127) / 128, 128>>>(x, emb);
    edge_prep_kernel<<<(NE + 255) / 256, 256>>>(ea, ei);
    node_meta_kernel<<<(NN + 255) / 256, 256>>>();
    csr_fill_kernel<<<(NE + 255) / 256, 256>>>(ei);

    int mtiles = (NN + 127) / 128;
    for (int b = 0; b < 2; b++) {
        rgcn_gather_kernel<<<(NN + 7) / 8, 256>>>();
        rgcn_gemm_tc<<<mtiles, 128, SMEM_SZ>>>(rw[b], rro[b], rb[b]);
        mf_gather_kernel<<<(NN + 7) / 8, 256>>>();
        if (b == 0)
            mf_gemm_tc<<<NTILES, 128, SMEM_SZ>>>(wl[b], bll[b], wr[b]);
        else
            mf_gemm_pool_tc<<<NTILES, 128, SMEM_SZ>>>(wl[b], bll[b], wr[b], batch);
    }

    mlp_kernel<<<NG / 8, 256>>>(l1w, l1b, l2w, l2b, out);
}

// round 17
// speedup vs baseline: 1.0161x; 1.0161x over previous
#include <cuda_runtime.h>
#include <cuda_bf16.h>
#include <cstdint>

#define NN 50000
#define NE 800000
#define NG 1024
#define NFEAT 32
#define NREL 4
#define NH 64
#define NO 16
#define MAXDEG 10
#define NTILES ((NN + 127) / 128 + MAXDEG)   // 401: upper bound on total bucket tiles

// padded bf16 tile stride (elements): 70 -> 35 words/row; fill-store bank = 3*row (coprime 32) -> conflict-free
#define AST 70
// dynamic smem layout (bytes)
#define OFF_NODES 0
#define OFF_AHI   1024
#define OFF_ALO   (OFF_AHI + 128 * AST * 2)   // 18944
#define OFF_BHI   (OFF_ALO + 128 * AST * 2)   // 36864
#define OFF_BLO   (OFF_BHI + 64 * AST * 2)    // 45824
#define SMEM_SZ   (OFF_BLO + 64 * AST * 2)    // 54784

// ---------------- scratch (device globals) ----------------
__device__ float g_h[NN * NH];
__device__ float g_hmid[NN * NH];
__device__ float g_aggm[NN * NH];
__device__ float g_agg[NN * NREL * NH];
__device__ float g_pool[NG * NH];
__device__ float g_invw[NN * NREL];
__device__ int   g_cnt[NN * NREL];
__device__ int   g_off4[NN * NREL];
__device__ int   g_cur4[NN * NREL];
__device__ int   g_indeg[NN];
__device__ int   g_off[NN];
__device__ int   g_csr[NE];
__device__ int   g_rel[NE];
__device__ int   g_bcnt[MAXDEG + 1];
__device__ int   g_bnodes[(MAXDEG + 1) * NN];  // fixed region per degree bucket
__device__ int   g_total;

// ---------------- mma.sync helper ----------------
static __device__ __forceinline__ void mma16816(float* c, const uint32_t* a, const uint32_t* b) {
    asm volatile(
        "mma.sync.aligned.m16n8k16.row.col.f32.bf16.bf16.f32 "
        "{%0,%1,%2,%3}, {%4,%5,%6,%7}, {%8,%9}, {%0,%1,%2,%3};\n"
        : "+f"(c[0]), "+f"(c[1]), "+f"(c[2]), "+f"(c[3])
        : "r"(a[0]), "r"(a[1]), "r"(a[2]), "r"(a[3]), "r"(b[0]), "r"(b[1]));
}
static __device__ __forceinline__ uint32_t lds_u32(const __nv_bfloat16* p) {
    return *reinterpret_cast<const uint32_t*>(p);
}

// split one float4 (row segment of 4 k-values) into bf16 hi/lo into padded tiles
static __device__ __forceinline__ void split_store4(__nv_bfloat16* Ah, __nv_bfloat16* Al,
                                                    int row, int k, float4 v) {
    __nv_bfloat16 hx = __float2bfloat16_rn(v.x);
    __nv_bfloat16 hy = __float2bfloat16_rn(v.y);
    __nv_bfloat16 hz = __float2bfloat16_rn(v.z);
    __nv_bfloat16 hw = __float2bfloat16_rn(v.w);
    __nv_bfloat16 lx = __float2bfloat16_rn(v.x - __bfloat162float(hx));
    __nv_bfloat16 ly = __float2bfloat16_rn(v.y - __bfloat162float(hy));
    __nv_bfloat16 lz = __float2bfloat16_rn(v.z - __bfloat162float(hz));
    __nv_bfloat16 lw = __float2bfloat16_rn(v.w - __bfloat162float(hw));
    __nv_bfloat162* ph = reinterpret_cast<__nv_bfloat162*>(Ah + row * AST + k);
    __nv_bfloat162* pl = reinterpret_cast<__nv_bfloat162*>(Al + row * AST + k);
    ph[0] = __nv_bfloat162(hx, hy); ph[1] = __nv_bfloat162(hz, hw);
    pl[0] = __nv_bfloat162(lx, ly); pl[1] = __nv_bfloat162(lz, lw);
}

// transpose-load 64x64 fp32 weight chunk [k][n] -> [n][k] bf16 hi/lo padded tiles
static __device__ __forceinline__ void load_b_chunk(__nv_bfloat16* Bh, __nv_bfloat16* Bl,
                                                    const float* __restrict__ bsrc, int tid) {
#pragma unroll
    for (int i = 0; i < 32; i++) {
        int idx = i * 128 + tid;
        int k = idx >> 6, n = idx & 63;
        float val = __ldg(&bsrc[k * 64 + n]);
        __nv_bfloat16 hb = __float2bfloat16_rn(val);
        __nv_bfloat16 lb = __float2bfloat16_rn(val - __bfloat162float(hb));
        Bh[n * AST + k] = hb;
        Bl[n * AST + k] = lb;
    }
}

// warp-level 32x64 mma over one K=64 chunk; acc[2][8][4]
static __device__ __forceinline__ void mma_chunk(float acc[2][8][4],
                                                 const __nv_bfloat16* Ah, const __nv_bfloat16* Al,
                                                 const __nv_bfloat16* Bh, const __nv_bfloat16* Bl,
                                                 int wid, int lane) {
    int g = lane >> 2, t = lane & 3;
#pragma unroll
    for (int ks = 0; ks < 4; ks++) {
        int kb = ks * 16 + 2 * t;
        uint32_t ah[2][4], al[2][4];
#pragma unroll
        for (int mt = 0; mt < 2; mt++) {
            const __nv_bfloat16* ph = Ah + (wid * 32 + mt * 16 + g) * AST + kb;
            const __nv_bfloat16* pl = Al + (wid * 32 + mt * 16 + g) * AST + kb;
            ah[mt][0] = lds_u32(ph);            ah[mt][1] = lds_u32(ph + 8 * AST);
            ah[mt][2] = lds_u32(ph + 8);        ah[mt][3] = lds_u32(ph + 8 * AST + 8);
            al[mt][0] = lds_u32(pl);            al[mt][1] = lds_u32(pl + 8 * AST);
            al[mt][2] = lds_u32(pl + 8);        al[mt][3] = lds_u32(pl + 8 * AST + 8);
        }
#pragma unroll
        for (int nt = 0; nt < 8; nt++) {
            const __nv_bfloat16* qh = Bh + (nt * 8 + g) * AST + kb;
            const __nv_bfloat16* ql = Bl + (nt * 8 + g) * AST + kb;
            uint32_t bh[2] = {lds_u32(qh), lds_u32(qh + 8)};
            uint32_t bl[2] = {lds_u32(ql), lds_u32(ql + 8)};
#pragma unroll
            for (int mt = 0; mt < 2; mt++) {
                mma16816(acc[mt][nt], ah[mt], bh);
                mma16816(acc[mt][nt], ah[mt], bl);
                mma16816(acc[mt][nt], al[mt], bh);
            }
        }
    }
}

// ---------------- zero scratch ----------------
__global__ void zero_kernel() {
    int i = blockIdx.x * 256 + threadIdx.x;
    if (i < NN * NREL) { g_cnt[i] = 0; g_cur4[i] = 0; }
    if (i < NG * NH) g_pool[i] = 0.f;
    if (i <= MAXDEG) g_bcnt[i] = 0;
    if (i == 0) g_total = 0;
}

// ---------------- node init ----------------
__global__ void node_init_kernel(const float* __restrict__ x, const float* __restrict__ emb) {
    int n = blockIdx.x * 128 + threadIdx.x;
    if (n >= NN) return;
    const float4* xr = (const float4*)(x + (size_t)n * NFEAT);
    float best = -1e30f; int bi = 0;
#pragma unroll
    for (int q = 0; q < NFEAT / 4; q++) {
        float4 v = xr[q];
        if (v.x > best) { best = v.x; bi = q * 4 + 0; }
        if (v.y > best) { best = v.y; bi = q * 4 + 1; }
        if (v.z > best) { best = v.z; bi = q * 4 + 2; }
        if (v.w > best) { best = v.w; bi = q * 4 + 3; }
    }
    const float4* er = (const float4*)(emb + bi * NH);
    float4* hr = (float4*)(g_h + (size_t)n * NH);
#pragma unroll
    for (int q = 0; q < NH / 4; q++) hr[q] = er[q];
}

// ---------------- edge prep ----------------
__global__ void edge_prep_kernel(const float* __restrict__ ea, const int* __restrict__ ei) {
    int e = blockIdx.x * 256 + threadIdx.x;
    if (e >= NE) return;
    float4 a = ((const float4*)ea)[e];
    int rel = 0; float best = a.x;
    if (a.y > best) { best = a.y; rel = 1; }
    if (a.z > best) { best = a.z; rel = 2; }
    if (a.w > best) { best = a.w; rel = 3; }
    g_rel[e] = rel;
    atomicAdd(&g_cnt[ei[NE + e] * NREL + rel], 1);
}

// ---------------- node meta: inv weights, CSR offsets, degree-bucket count+fill fused ----------------
__global__ void node_meta_kernel() {
    int n = blockIdx.x * 256 + threadIdx.x;
    int lane = threadIdx.x & 31;
    bool valid = n < NN;
    int c0 = 0, c1 = 0, c2 = 0, c3 = 0;
    if (valid) {
        c0 = g_cnt[n * NREL + 0]; c1 = g_cnt[n * NREL + 1];
        c2 = g_cnt[n * NREL + 2]; c3 = g_cnt[n * NREL + 3];
    }
    int ind = c0 + c1 + c2 + c3;
    if (valid) {
        g_invw[n * NREL + 0] = c0 ? 1.0f / (float)c0 : 0.f;
        g_invw[n * NREL + 1] = c1 ? 1.0f / (float)c1 : 0.f;
        g_invw[n * NREL + 2] = c2 ? 1.0f / (float)c2 : 0.f;
        g_invw[n * NREL + 3] = c3 ? 1.0f / (float)c3 : 0.f;
        g_indeg[n] = ind;
    }
    int incl = ind;
#pragma unroll
    for (int o = 1; o < 32; o <<= 1) {
        int t = __shfl_up_sync(0xffffffffu, incl, o);
        if (lane >= o) incl += t;
    }
    int wsum = __shfl_sync(0xffffffffu, incl, 31);
    int base = 0;
    if (lane == 0) base = atomicAdd(&g_total, wsum);
    base = __shfl_sync(0xffffffffu, base, 0);
    if (valid) {
        int off = base + incl - ind;
        g_off[n] = off;
        g_off4[n * NREL + 0] = off;
        g_off4[n * NREL + 1] = off + c0;
        g_off4[n * NREL + 2] = off + c0 + c1;
        g_off4[n * NREL + 3] = off + c0 + c1 + c2;
    }
    int d = min(ind, MAXDEG);
    unsigned vm = __ballot_sync(0xffffffffu, valid);
    unsigned m = __match_any_sync(0xffffffffu, d) & vm;
    if (valid) {
        int leader = __ffs(m) - 1;
        int rank = __popc(m & ((1u << lane) - 1));
        int bbase = 0;
        if (lane == leader) bbase = atomicAdd(&g_bcnt[d], __popc(m));
        bbase = __shfl_sync(0xffffffffu, bbase, leader);
        g_bnodes[d * NN + bbase + rank] = n;
    }
}

__global__ void csr_fill_kernel(const int* __restrict__ ei) {
    int e = blockIdx.x * 256 + threadIdx.x;
    if (e >= NE) return;
    int t = ei[NE + e];
    int slot = t * NREL + g_rel[e];
    int pos = g_off4[slot] + atomicAdd(&g_cur4[slot], 1);
    g_csr[pos] = ei[e];
}

// ---------------- RGCN gather: one node per warp, float2 per lane ----------------
__global__ __launch_bounds__(256) void rgcn_gather_kernel() {
    int wid = threadIdx.x >> 5, lane = threadIdx.x & 31;
    int node = blockIdx.x * 8 + wid;
    if (node >= NN) return;
    const float2* h2 = (const float2*)g_h;   // row stride 32 float2
    const int* off4 = g_off4 + node * NREL;
    const int* cnt4 = g_cnt + node * NREL;
    const float* iw = g_invw + node * NREL;
    float2* o = (float2*)(g_agg + ((size_t)node * NREL) * NH) + lane;
#pragma unroll
    for (int r = 0; r < NREL; r++) {
        int beg = off4[r];
        int end = beg + cnt4[r];
        float a0 = 0.f, a1 = 0.f;
        int i = beg;
        for (; i + 4 <= end; i += 4) {
            int s0 = __ldg(&g_csr[i]),     s1 = __ldg(&g_csr[i + 1]);
            int s2 = __ldg(&g_csr[i + 2]), s3 = __ldg(&g_csr[i + 3]);
            float2 v0 = __ldg(&h2[s0 * 32 + lane]);
            float2 v1 = __ldg(&h2[s1 * 32 + lane]);
            float2 v2 = __ldg(&h2[s2 * 32 + lane]);
            float2 v3 = __ldg(&h2[s3 * 32 + lane]);
            a0 += fmaxf(v0.x, 0.f) + fmaxf(v1.x, 0.f) + fmaxf(v2.x, 0.f) + fmaxf(v3.x, 0.f);
            a1 += fmaxf(v0.y, 0.f) + fmaxf(v1.y, 0.f) + fmaxf(v2.y, 0.f) + fmaxf(v3.y, 0.f);
        }
        for (; i < end; i++) {
            float2 v = __ldg(&h2[__ldg(&g_csr[i]) * 32 + lane]);
            a0 += fmaxf(v.x, 0.f);
            a1 += fmaxf(v.y, 0.f);
        }
        float w = iw[r];
        o[r * 32] = make_float2(a0 * w, a1 * w);
    }
}

// ---------------- RGCN GEMM via mma.sync bf16-split (128 threads, 5 K-chunks) ----------------
__global__ __launch_bounds__(128) void rgcn_gemm_tc(const float* __restrict__ W,
                                                    const float* __restrict__ Wroot,
                                                    const float* __restrict__ bias) {
    extern __shared__ __align__(16) char smem[];
    __nv_bfloat16* Ah = (__nv_bfloat16*)(smem + OFF_AHI);
    __nv_bfloat16* Al = (__nv_bfloat16*)(smem + OFF_ALO);
    __nv_bfloat16* Bh = (__nv_bfloat16*)(smem + OFF_BHI);
    __nv_bfloat16* Bl = (__nv_bfloat16*)(smem + OFF_BLO);
    int tid = threadIdx.x, wid = tid >> 5, lane = tid & 31;
    int row = blockIdx.x * 128 + tid;

    float acc[2][8][4];
#pragma unroll
    for (int a = 0; a < 2; a++)
#pragma unroll
        for (int b = 0; b < 8; b++)
#pragma unroll
            for (int c = 0; c < 4; c++) acc[a][b][c] = 0.f;

    for (int c = 0; c < 5; c++) {
        if (c) __syncthreads();
        if (row < NN) {
            const float4* src = (c < 4)
                ? (const float4*)(g_agg + ((size_t)row * NREL + c) * NH)
                : (const float4*)(g_h + (size_t)row * NH);
            bool rl = (c == 4);
#pragma unroll
            for (int q = 0; q < 16; q++) {
                float4 v = src[q];
                if (rl) { v.x = fmaxf(v.x, 0.f); v.y = fmaxf(v.y, 0.f);
                          v.z = fmaxf(v.z, 0.f); v.w = fmaxf(v.w, 0.f); }
                split_store4(Ah, Al, tid, q * 4, v);
            }
        } else {
#pragma unroll
            for (int q = 0; q < 16; q++)
                split_store4(Ah, Al, tid, q * 4, make_float4(0.f, 0.f, 0.f, 0.f));
        }
        load_b_chunk(Bh, Bl, (c < 4) ? (W + c * NH * NH) : Wroot, tid);
        __syncthreads();
        mma_chunk(acc, Ah, Al, Bh, Bl, wid, lane);
    }

    int g = lane >> 2, t = lane & 3;
#pragma unroll
    for (int mt = 0; mt < 2; mt++) {
        int r0 = blockIdx.x * 128 + wid * 32 + mt * 16 + g;
        int r1 = r0 + 8;
#pragma unroll
        for (int nt = 0; nt < 8; nt++) {
            int col = nt * 8 + 2 * t;
            float b0 = __ldg(&bias[col]), b1 = __ldg(&bias[col + 1]);
            if (r0 < NN)
                *(float2*)(g_hmid + (size_t)r0 * NH + col) =
                    make_float2(acc[mt][nt][0] + b0, acc[mt][nt][1] + b1);
            if (r1 < NN)
                *(float2*)(g_hmid + (size_t)r1 * NH + col) =
                    make_float2(acc[mt][nt][2] + b0, acc[mt][nt][3] + b1);
        }
    }
}

// ---------------- MFConv gather: one node per warp, float2 per lane ----------------
__global__ __launch_bounds__(256) void mf_gather_kernel() {
    int wid = threadIdx.x >> 5, lane = threadIdx.x & 31;
    int node = blockIdx.x * 8 + wid;
    if (node >= NN) return;
    const float2* h2 = (const float2*)g_hmid;
    int beg = g_off[node];
    int end = beg + g_indeg[node];
    float a0 = 0.f, a1 = 0.f;
    int i = beg;
    for (; i + 4 <= end; i += 4) {
        int s0 = __ldg(&g_csr[i]),     s1 = __ldg(&g_csr[i + 1]);
        int s2 = __ldg(&g_csr[i + 2]), s3 = __ldg(&g_csr[i + 3]);
        float2 v0 = __ldg(&h2[s0 * 32 + lane]);
        float2 v1 = __ldg(&h2[s1 * 32 + lane]);
        float2 v2 = __ldg(&h2[s2 * 32 + lane]);
        float2 v3 = __ldg(&h2[s3 * 32 + lane]);
        a0 += fmaxf(v0.x, 0.f) + fmaxf(v1.x, 0.f) + fmaxf(v2.x, 0.f) + fmaxf(v3.x, 0.f);
        a1 += fmaxf(v0.y, 0.f) + fmaxf(v1.y, 0.f) + fmaxf(v2.y, 0.f) + fmaxf(v3.y, 0.f);
    }
    for (; i < end; i++) {
        float2 v = __ldg(&h2[__ldg(&g_csr[i]) * 32 + lane]);
        a0 += fmaxf(v.x, 0.f);
        a1 += fmaxf(v.y, 0.f);
    }
    ((float2*)(g_aggm + (size_t)node * NH))[lane] = make_float2(a0, a1);
}

// ---------------- MFConv GEMM via mma.sync (flattened 1D grid over bucket tiles) ----------------
__global__ __launch_bounds__(128) void mf_gemm_tc(const float* __restrict__ Wl,
                                                  const float* __restrict__ blv,
                                                  const float* __restrict__ Wr) {
    // map blockIdx.x -> (bucket d, tile offset t0); counts are device-side
    int bid = blockIdx.x;
    int d = -1, t0 = 0, acc0 = 0;
#pragma unroll
    for (int dd = 0; dd <= MAXDEG; dd++) {
        int tiles = (g_bcnt[dd] + 127) >> 7;
        if (d < 0 && bid < acc0 + tiles) { d = dd; t0 = (bid - acc0) * 128; }
        acc0 += tiles;
    }
    if (d < 0) return;
    int cnt = g_bcnt[d];

    extern __shared__ __align__(16) char smem[];
    int* nodes = (int*)(smem + OFF_NODES);
    __nv_bfloat16* Ah = (__nv_bfloat16*)(smem + OFF_AHI);
    __nv_bfloat16* Al = (__nv_bfloat16*)(smem + OFF_ALO);
    __nv_bfloat16* Bh = (__nv_bfloat16*)(smem + OFF_BHI);
    __nv_bfloat16* Bl = (__nv_bfloat16*)(smem + OFF_BLO);
    int tid = threadIdx.x, wid = tid >> 5, lane = tid & 31;
    {
        int idx = t0 + tid;
        nodes[tid] = (idx < cnt) ? g_bnodes[d * NN + idx] : -1;
    }
    __syncthreads();
    int mynode = nodes[tid];

    float acc[2][8][4];
#pragma unroll
    for (int a = 0; a < 2; a++)
#pragma unroll
        for (int b = 0; b < 8; b++)
#pragma unroll
            for (int cc = 0; cc < 4; cc++) acc[a][b][cc] = 0.f;

    for (int c = 0; c < 2; c++) {
        if (c) __syncthreads();
        if (mynode >= 0) {
            const float4* src = c ? (const float4*)(g_hmid + (size_t)mynode * NH)
                                  : (const float4*)(g_aggm + (size_t)mynode * NH);
            bool rl = (c == 1);
#pragma unroll
            for (int q = 0; q < 16; q++) {
                float4 v = src[q];
                if (rl) { v.x = fmaxf(v.x, 0.f); v.y = fmaxf(v.y, 0.f);
                          v.z = fmaxf(v.z, 0.f); v.w = fmaxf(v.w, 0.f); }
                split_store4(Ah, Al, tid, q * 4, v);
            }
        } else {
#pragma unroll
            for (int q = 0; q < 16; q++)
                split_store4(Ah, Al, tid, q * 4, make_float4(0.f, 0.f, 0.f, 0.f));
        }
        load_b_chunk(Bh, Bl, (c ? Wr : Wl) + d * NH * NH, tid);
        __syncthreads();
        mma_chunk(acc, Ah, Al, Bh, Bl, wid, lane);
    }

    int g = lane >> 2, t = lane & 3;
    const float* bb = blv + d * NH;
#pragma unroll
    for (int mt = 0; mt < 2; mt++) {
        int i0 = wid * 32 + mt * 16 + g;
        int n0 = nodes[i0], n1 = nodes[i0 + 8];
#pragma unroll
        for (int nt = 0; nt < 8; nt++) {
            int col = nt * 8 + 2 * t;
            float b0 = __ldg(&bb[col]), b1 = __ldg(&bb[col + 1]);
            if (n0 >= 0)
                *(float2*)(g_h + (size_t)n0 * NH + col) =
                    make_float2(acc[mt][nt][0] + b0, acc[mt][nt][1] + b1);
            if (n1 >= 0)
                *(float2*)(g_h + (size_t)n1 * NH + col) =
                    make_float2(acc[mt][nt][2] + b0, acc[mt][nt][3] + b1);
        }
    }
}

// ---------------- global add pool ----------------
__global__ void pool_kernel(const int* __restrict__ batch) {
    int i = blockIdx.x * 256 + threadIdx.x;
    int grp = i >> 6;
    if (grp * 4 >= NN) return;
    int dim = i & 63;
    int n0 = grp * 4;
    int curb = batch[n0];
    float vsum = g_h[(size_t)n0 * NH + dim];
#pragma unroll
    for (int j = 1; j < 4; j++) {
        int n = n0 + j;
        if (n >= NN) break;
        int b = batch[n];
        float v = g_h[(size_t)n * NH + dim];
        if (b == curb) vsum += v;
        else { atomicAdd(&g_pool[curb * NH + dim], vsum); curb = b; vsum = v; }
    }
    atomicAdd(&g_pool[curb * NH + dim], vsum);
}

// ---------------- head MLP ----------------
__global__ __launch_bounds__(256) void mlp_kernel(const float* __restrict__ l1w, const float* __restrict__ l1b,
                                                  const float* __restrict__ l2w, const float* __restrict__ l2b,
                                                  float* __restrict__ out) {
    __shared__ float s1[NH * NH];
    __shared__ float s2[NH * NO];
    __shared__ float sg[8][NH];
    int tid = threadIdx.x, lane = tid & 31, w = tid >> 5;
#pragma unroll
    for (int i = 0; i < 16; i++) s1[i * 256 + tid] = l1w[i * 256 + tid];
#pragma unroll
    for (int i = 0; i < 4; i++) s2[i * 256 + tid] = l2w[i * 256 + tid];
    int gidx = blockIdx.x * 8 + w;
    sg[w][lane] = g_pool[gidx * NH + lane];
    sg[w][lane + 32] = g_pool[gidx * NH + lane + 32];
    __syncthreads();
    float t0 = l1b[lane], t1 = l1b[lane + 32];
#pragma unroll 8
    for (int k = 0; k < NH; k++) {
        float gv = sg[w][k];
        t0 += gv * s1[k * NH + lane];
        t1 += gv * s1[k * NH + lane + 32];
    }
    t0 = fmaxf(t0, 0.f); t1 = fmaxf(t1, 0.f);
    __syncwarp();
    sg[w][lane] = t0; sg[w][lane + 32] = t1;
    __syncwarp();
    if (lane < NO) {
        float acc = l2b[lane];
#pragma unroll 8
        for (int j = 0; j < NH; j++) acc += sg[w][j] * s2[j * NO + lane];
        out[gidx * NO + lane] = acc;
    }
}

// ---------------- launch ----------------
extern "C" void kernel_launch(void* const* d_in, const int* in_sizes, int n_in,
                              void* d_out, int out_size) {
    const float *x, *ea, *emb, *l1w, *l1b, *l2w, *l2b;
    const int *ei, *batch;
    const float *rw[2], *rro[2], *rb[2], *wl[2], *bll[2], *wr[2];

    if (in_sizes[1] == NE * NREL) {
        x = (const float*)d_in[0];  ea = (const float*)d_in[1];
        ei = (const int*)d_in[2];   batch = (const int*)d_in[3];
        emb = (const float*)d_in[4];
        l1w = (const float*)d_in[5]; l1b = (const float*)d_in[6];
        l2w = (const float*)d_in[7]; l2b = (const float*)d_in[8];
        for (int b = 0; b < 2; b++) {
            int k = 9 + 6 * b;
            rw[b]  = (const float*)d_in[k + 0];
            rro[b] = (const float*)d_in[k + 1];
            rb[b]  = (const float*)d_in[k + 2];
            wl[b]  = (const float*)d_in[k + 3];
            bll[b] = (const float*)d_in[k + 4];
            wr[b]  = (const float*)d_in[k + 5];
        }
    } else {
        x = (const float*)d_in[0];  ei = (const int*)d_in[1];
        ea = (const float*)d_in[2]; batch = (const int*)d_in[3];
        emb = (const float*)d_in[4];
        for (int b = 0; b < 2; b++) {
            int k = 5 + 6 * b;
            rw[b]  = (const float*)d_in[k + 0];
            rro[b] = (const float*)d_in[k + 1];
            rb[b]  = (const float*)d_in[k + 2];
            wl[b]  = (const float*)d_in[k + 3];
            bll[b] = (const float*)d_in[k + 4];
            wr[b]  = (const float*)d_in[k + 5];
        }
        l1w = (const float*)d_in[17]; l1b = (const float*)d_in[18];
        l2w = (const float*)d_in[19]; l2b = (const float*)d_in[20];
    }
    float* out = (float*)d_out;

    cudaFuncSetAttribute(rgcn_gemm_tc, cudaFuncAttributeMaxDynamicSharedMemorySize, SMEM_SZ);
    cudaFuncSetAttribute(mf_gemm_tc, cudaFuncAttributeMaxDynamicSharedMemorySize, SMEM_SZ);

    zero_kernel<<<(NN * NREL + 255) / 256, 256>>>();
    node_init_kernel<<<(NN + 127) / 128, 128>>>(x, emb);
    edge_prep_kernel<<<(NE + 255) / 256, 256>>>(ea, ei);
    node_meta_kernel<<<(NN + 255) / 256, 256>>>();
    csr_fill_kernel<<<(NE + 255) / 256, 256>>>(ei);

    int mtiles = (NN + 127) / 128;
    for (int b = 0; b < 2; b++) {
        rgcn_gather_kernel<<<(NN + 7) / 8, 256>>>();
        rgcn_gemm_tc<<<mtiles, 128, SMEM_SZ>>>(rw[b], rro[b], rb[b]);
        mf_gather_kernel<<<(NN + 7) / 8, 256>>>();
        mf_gemm_tc<<<NTILES, 128, SMEM_SZ>>>(wl[b], bll[b], wr[b]);
    }

    pool_kernel<<<(NN * NH / 4 + 255) / 256, 256>>>(batch);
    mlp_kernel<<<NG / 8, 256>>>(l1w, l1b, l2w, l2b, out);
}